// round 7
// baseline (speedup 1.0000x reference)
#include <cuda_runtime.h>
#include <cuda_fp16.h>
#include <math.h>
#include <stdint.h>

// Problem constants
#define T_TOK 2048
#define H_DIM 1024
#define E_EXP 32
#define I_DIM 2048

#define BM 128
#define BK 16
#define NTHREADS 256
#define MAX_TILES 64
#define SROW_H 24   // halves per smem row (16 + 8 pad) -> conflict-free

// -------- scratch (static device globals) --------
__device__ float g_mix[T_TOK * 96];
__device__ float g_topw[T_TOK * 2];
__device__ int   g_counts[E_EXP];
__device__ int   g_list[E_EXP * T_TOK];
__device__ int   g_tile_e[MAX_TILES];
__device__ int   g_tile_m0[MAX_TILES];
__device__ int   g_ntiles;
__device__ float g_act [(size_t)T_TOK * 2 * I_DIM];     // SwiGLU act   (32 MB)
__device__ float g_outp[(size_t)T_TOK * 2 * H_DIM];     // per-pair out (16 MB)

// ------------------------------------------------------------------
__global__ void zero_counts_kernel() {
    if (threadIdx.x < E_EXP) g_counts[threadIdx.x] = 0;
}

// ------------------------------------------------------------------
// mix = x @ wqkv^T   [2048, 96], K=1024  (fp32, small)
__global__ __launch_bounds__(256) void mix_gemm_kernel(
    const float* __restrict__ x, const float* __restrict__ wqkv)
{
    __shared__ float As[16][64];
    __shared__ float Bs[16][64];
    const int N = 96, K = H_DIM;
    int m0 = blockIdx.y * 64, n0 = blockIdx.x * 64;
    int tid = threadIdx.x;
    int tx = tid & 15, ty = tid >> 4;
    int lm = tid >> 2, lk = (tid & 3) * 4;

    const float* Arow = x + (size_t)(m0 + lm) * K;
    int brow = n0 + lm;
    const float* Brow = wqkv + (size_t)min(brow, N - 1) * K;
    bool bvalid = brow < N;

    float acc[4][4] = {};
    for (int k0 = 0; k0 < K; k0 += 16) {
        float4 av = *(const float4*)(Arow + k0 + lk);
        float4 bv = bvalid ? *(const float4*)(Brow + k0 + lk) : make_float4(0.f,0.f,0.f,0.f);
        As[lk+0][lm]=av.x; As[lk+1][lm]=av.y; As[lk+2][lm]=av.z; As[lk+3][lm]=av.w;
        Bs[lk+0][lm]=bv.x; Bs[lk+1][lm]=bv.y; Bs[lk+2][lm]=bv.z; Bs[lk+3][lm]=bv.w;
        __syncthreads();
        #pragma unroll
        for (int kk = 0; kk < 16; kk++) {
            float4 a = *(const float4*)&As[kk][ty*4];
            float4 b = *(const float4*)&Bs[kk][tx*4];
            float ar[4] = {a.x,a.y,a.z,a.w};
            float br[4] = {b.x,b.y,b.z,b.w};
            #pragma unroll
            for (int i = 0; i < 4; i++)
                #pragma unroll
                for (int j = 0; j < 4; j++)
                    acc[i][j] += ar[i] * br[j];
        }
        __syncthreads();
    }
    #pragma unroll
    for (int i = 0; i < 4; i++) {
        int m = m0 + ty*4 + i;
        #pragma unroll
        for (int j = 0; j < 4; j++) {
            int n = n0 + tx*4 + j;
            if (n < N) g_mix[(size_t)m * 96 + n] = acc[i][j];
        }
    }
}

// ------------------------------------------------------------------
__global__ void route_kernel()
{
    int t = blockIdx.x * 4 + (threadIdx.x >> 5);
    int lane = threadIdx.x & 31;
    if (t >= T_TOK) return;
    const float* mix = g_mix + (size_t)t * 96;
    float q  = mix[lane];
    float kf = mix[32 + lane];
    float vf = mix[64 + lane];

    float m = -INFINITY;
    #pragma unroll
    for (int f = 0; f < 32; f++) {
        float kk = __shfl_sync(0xffffffffu, kf, f);
        m = fmaxf(m, q * kk);
    }
    float s = 0.f, num = 0.f;
    #pragma unroll
    for (int f = 0; f < 32; f++) {
        float kk = __shfl_sync(0xffffffffu, kf, f);
        float vv = __shfl_sync(0xffffffffu, vf, f);
        float p = expf(q * kk - m);
        s += p; num += p * vv;
    }
    float logit = num / s;

    float v1 = logit; int i1 = lane;
    #pragma unroll
    for (int off = 16; off > 0; off >>= 1) {
        float ov = __shfl_xor_sync(0xffffffffu, v1, off);
        int   oi = __shfl_xor_sync(0xffffffffu, i1, off);
        if (ov > v1 || (ov == v1 && oi < i1)) { v1 = ov; i1 = oi; }
    }
    float mval = (lane == i1) ? -INFINITY : logit;
    float v2 = mval; int i2 = lane;
    #pragma unroll
    for (int off = 16; off > 0; off >>= 1) {
        float ov = __shfl_xor_sync(0xffffffffu, v2, off);
        int   oi = __shfl_xor_sync(0xffffffffu, i2, off);
        if (ov > v2 || (ov == v2 && oi < i2)) { v2 = ov; i2 = oi; }
    }

    if (lane == 0) {
        float e2 = expf(v2 - v1);
        float inv = 1.f / (1.f + e2);
        g_topw[t*2 + 0] = inv;
        g_topw[t*2 + 1] = e2 * inv;
        int p1 = atomicAdd(&g_counts[i1], 1);
        g_list[i1 * T_TOK + p1] = t*2 + 0;
        int p2 = atomicAdd(&g_counts[i2], 1);
        g_list[i2 * T_TOK + p2] = t*2 + 1;
    }
}

// ------------------------------------------------------------------
__global__ void build_tiles_kernel()
{
    int e = threadIdx.x;
    int ne = g_counts[e];
    int ct = (ne + BM - 1) / BM;
    int pre = ct;
    #pragma unroll
    for (int off = 1; off < 32; off <<= 1) {
        int v = __shfl_up_sync(0xffffffffu, pre, off);
        if (e >= off) pre += v;
    }
    int start = pre - ct;
    for (int i = 0; i < ct; i++) {
        g_tile_e[start + i]  = e;
        g_tile_m0[start + i] = i * BM;
    }
    if (e == 31) g_ntiles = pre;
}

// ------------------------------------------------------------------
__device__ __forceinline__ uint32_t packh2(float x, float y) {
    __half2 h = __floats2half2_rn(x, y);
    return *(uint32_t*)&h;
}
__device__ __forceinline__ uint4 pack8(float4 a, float4 b) {
    return make_uint4(packh2(a.x,a.y), packh2(a.z,a.w), packh2(b.x,b.y), packh2(b.z,b.w));
}

#define MMA16816(d, a0,a1,a2,a3, b0,b1)                                   \
    asm volatile(                                                          \
        "mma.sync.aligned.m16n8k16.row.col.f32.f16.f16.f32 "              \
        "{%0,%1,%2,%3}, {%4,%5,%6,%7}, {%8,%9}, {%0,%1,%2,%3};"           \
        : "+f"(d[0]), "+f"(d[1]), "+f"(d[2]), "+f"(d[3])                   \
        : "r"(a0), "r"(a1), "r"(a2), "r"(a3), "r"(b0), "r"(b1))

// ------------------------------------------------------------------
// GEMM1 fused with SwiGLU (fp16 tensor cores).
// act[code, n] = silu(x_t . wg_n) * (x_t . wu_n),  n in [n0, n0+64)
// Each CTA: 128 rows x 64 act cols; loads gate rows n0..n0+63 and up
// rows I+n0..I+n0+63. Warp grid 4x2; each warp 32 rows x 32 cols, g+u.
__global__ __launch_bounds__(NTHREADS, 2) void gemm1_fused_kernel(
    const float* __restrict__ x, const float* __restrict__ ws)
{
    int tile = blockIdx.y;
    if (tile >= g_ntiles) return;
    int e  = g_tile_e[tile];
    int m0 = g_tile_m0[tile];
    int ne = g_counts[e];
    int n0 = blockIdx.x * 64;

    __shared__ uint16_t As[2][128][SROW_H];
    __shared__ uint16_t Bg[2][64][SROW_H];
    __shared__ uint16_t Bu[2][64][SROW_H];

    const float* We = ws + (size_t)e * (2 * I_DIM) * H_DIM;

    int tid = threadIdx.x;
    int lr  = tid & 127;
    int lc8 = (tid >> 7) * 8;

    int code0 = g_list[e * T_TOK + min(m0 + lr, ne - 1)];
    const float* Ap = x + (size_t)(code0 >> 1) * H_DIM + lc8;
    const float* Bp = (lr < 64)
        ? We + (size_t)(n0 + lr) * H_DIM + lc8
        : We + (size_t)(I_DIM + n0 + (lr - 64)) * H_DIM + lc8;
    uint16_t* bd0 = (lr < 64) ? &Bg[0][lr][0] : &Bu[0][lr - 64][0];
    uint16_t* bd1 = (lr < 64) ? &Bg[1][lr][0] : &Bu[1][lr - 64][0];

    int wid = tid >> 5, lane = tid & 31;
    int wm = wid >> 1, wn = wid & 1;       // 4 x 2 warp grid
    int qr = lane >> 2, qc = lane & 3;

    float accg[2][4][4] = {};
    float accu[2][4][4] = {};

    float4 ra0 = *(const float4*)(Ap);
    float4 ra1 = *(const float4*)(Ap + 4);
    float4 rb0 = *(const float4*)(Bp);
    float4 rb1 = *(const float4*)(Bp + 4);

    int p = 0;
    for (int k0 = 0; k0 < H_DIM; k0 += BK) {
        *(uint4*)&As[p][lr][lc8] = pack8(ra0, ra1);
        uint16_t* bd = p ? bd1 : bd0;
        *(uint4*)(bd + lc8) = pack8(rb0, rb1);
        __syncthreads();

        if (k0 + BK < H_DIM) {
            ra0 = *(const float4*)(Ap + k0 + BK);
            ra1 = *(const float4*)(Ap + k0 + BK + 4);
            rb0 = *(const float4*)(Bp + k0 + BK);
            rb1 = *(const float4*)(Bp + k0 + BK + 4);
        }

        uint32_t af[2][4];
        #pragma unroll
        for (int mt = 0; mt < 2; mt++) {
            int mr = wm*32 + mt*16 + qr;
            af[mt][0] = *(const uint32_t*)&As[p][mr    ][2*qc];
            af[mt][1] = *(const uint32_t*)&As[p][mr + 8][2*qc];
            af[mt][2] = *(const uint32_t*)&As[p][mr    ][8 + 2*qc];
            af[mt][3] = *(const uint32_t*)&As[p][mr + 8][8 + 2*qc];
        }
        #pragma unroll
        for (int nt = 0; nt < 4; nt++) {
            int nr = wn*32 + nt*8 + qr;
            uint32_t bg0 = *(const uint32_t*)&Bg[p][nr][2*qc];
            uint32_t bg1 = *(const uint32_t*)&Bg[p][nr][8 + 2*qc];
            uint32_t bu0 = *(const uint32_t*)&Bu[p][nr][2*qc];
            uint32_t bu1 = *(const uint32_t*)&Bu[p][nr][8 + 2*qc];
            #pragma unroll
            for (int mt = 0; mt < 2; mt++) {
                MMA16816(accg[mt][nt], af[mt][0],af[mt][1],af[mt][2],af[mt][3], bg0, bg1);
                MMA16816(accu[mt][nt], af[mt][0],af[mt][1],af[mt][2],af[mt][3], bu0, bu1);
            }
        }
        p ^= 1;
    }

    // epilogue: silu(g)*u, rows r0=.., r1=r0+8; cols n0+wn*32+nt*8+2qc(+1)
    #pragma unroll
    for (int mt = 0; mt < 2; mt++) {
        int r0 = m0 + wm*32 + mt*16 + qr;
        int r1 = r0 + 8;
        bool v0 = r0 < ne, v1 = r1 < ne;
        int c0 = v0 ? g_list[e * T_TOK + r0] : 0;
        int c1 = v1 ? g_list[e * T_TOK + r1] : 0;
        float* d0 = g_act + (size_t)c0 * I_DIM + n0 + wn*32;
        float* d1 = g_act + (size_t)c1 * I_DIM + n0 + wn*32;
        #pragma unroll
        for (int nt = 0; nt < 4; nt++) {
            int col = nt*8 + 2*qc;
            if (v0) {
                float gx = accg[mt][nt][0], gy = accg[mt][nt][1];
                float ax = (gx / (1.f + expf(-gx))) * accu[mt][nt][0];
                float ay = (gy / (1.f + expf(-gy))) * accu[mt][nt][1];
                *(float2*)(d0 + col) = make_float2(ax, ay);
            }
            if (v1) {
                float gx = accg[mt][nt][2], gy = accg[mt][nt][3];
                float ax = (gx / (1.f + expf(-gx))) * accu[mt][nt][2];
                float ay = (gy / (1.f + expf(-gy))) * accu[mt][nt][3];
                *(float2*)(d1 + col) = make_float2(ax, ay);
            }
        }
    }
}

// ------------------------------------------------------------------
// GEMM2 (fp16 tensor cores): outp[code,:] = act[code,:] @ w2_e^T (K=2048, N=1024)
__global__ __launch_bounds__(NTHREADS, 2) void gemm2_tc_kernel(
    const float* __restrict__ w2s)
{
    constexpr int KDIM = I_DIM;
    constexpr int NTOT = H_DIM;

    int tile = blockIdx.y;
    if (tile >= g_ntiles) return;
    int e  = g_tile_e[tile];
    int m0 = g_tile_m0[tile];
    int ne = g_counts[e];
    int n0 = blockIdx.x * 128;

    __shared__ uint16_t As[2][128][SROW_H];
    __shared__ uint16_t Bs[2][128][SROW_H];

    const float* B = w2s + (size_t)e * NTOT * KDIM;

    int tid = threadIdx.x;
    int lr  = tid & 127;
    int lc8 = (tid >> 7) * 8;

    int code0 = g_list[e * T_TOK + min(m0 + lr, ne - 1)];
    const float* Ap = g_act + (size_t)code0 * KDIM + lc8;
    const float* Bp = B + (size_t)(n0 + lr) * KDIM + lc8;

    int wid = tid >> 5, lane = tid & 31;
    int wm = wid >> 2, wn = wid & 3;       // 2 x 4 warp grid (64x32 per warp)
    int qr = lane >> 2, qc = lane & 3;

    float acc[4][4][4] = {};

    float4 ra0 = *(const float4*)(Ap);
    float4 ra1 = *(const float4*)(Ap + 4);
    float4 rb0 = *(const float4*)(Bp);
    float4 rb1 = *(const float4*)(Bp + 4);

    int p = 0;
    for (int k0 = 0; k0 < KDIM; k0 += BK) {
        *(uint4*)&As[p][lr][lc8] = pack8(ra0, ra1);
        *(uint4*)&Bs[p][lr][lc8] = pack8(rb0, rb1);
        __syncthreads();

        if (k0 + BK < KDIM) {
            ra0 = *(const float4*)(Ap + k0 + BK);
            ra1 = *(const float4*)(Ap + k0 + BK + 4);
            rb0 = *(const float4*)(Bp + k0 + BK);
            rb1 = *(const float4*)(Bp + k0 + BK + 4);
        }

        uint32_t af[4][4];
        #pragma unroll
        for (int mt = 0; mt < 4; mt++) {
            int mr = wm*64 + mt*16 + qr;
            af[mt][0] = *(const uint32_t*)&As[p][mr    ][2*qc];
            af[mt][1] = *(const uint32_t*)&As[p][mr + 8][2*qc];
            af[mt][2] = *(const uint32_t*)&As[p][mr    ][8 + 2*qc];
            af[mt][3] = *(const uint32_t*)&As[p][mr + 8][8 + 2*qc];
        }
        #pragma unroll
        for (int nt = 0; nt < 4; nt++) {
            int nr = wn*32 + nt*8 + qr;
            uint32_t b0 = *(const uint32_t*)&Bs[p][nr][2*qc];
            uint32_t b1 = *(const uint32_t*)&Bs[p][nr][8 + 2*qc];
            #pragma unroll
            for (int mt = 0; mt < 4; mt++) {
                MMA16816(acc[mt][nt], af[mt][0],af[mt][1],af[mt][2],af[mt][3], b0, b1);
            }
        }
        p ^= 1;
    }

    #pragma unroll
    for (int mt = 0; mt < 4; mt++) {
        int r0 = m0 + wm*64 + mt*16 + qr;
        int r1 = r0 + 8;
        bool v0 = r0 < ne, v1 = r1 < ne;
        int c0 = v0 ? g_list[e * T_TOK + r0] : 0;
        int c1 = v1 ? g_list[e * T_TOK + r1] : 0;
        float* d0 = g_outp + (size_t)c0 * NTOT + n0 + wn*32;
        float* d1 = g_outp + (size_t)c1 * NTOT + n0 + wn*32;
        #pragma unroll
        for (int nt = 0; nt < 4; nt++) {
            int col = nt*8 + 2*qc;
            if (v0) *(float2*)(d0 + col) = make_float2(acc[mt][nt][0], acc[mt][nt][1]);
            if (v1) *(float2*)(d1 + col) = make_float2(acc[mt][nt][2], acc[mt][nt][3]);
        }
    }
}

// ------------------------------------------------------------------
__global__ void combine_kernel(float* __restrict__ y)
{
    int t = blockIdx.x;
    float w0 = g_topw[t*2 + 0];
    float w1 = g_topw[t*2 + 1];
    const float4* a = (const float4*)(g_outp + (size_t)(t*2    ) * H_DIM);
    const float4* b = (const float4*)(g_outp + (size_t)(t*2 + 1) * H_DIM);
    float4* o = (float4*)(y + (size_t)t * H_DIM);
    int i = threadIdx.x;
    float4 av = a[i], bv = b[i];
    float4 r;
    r.x = w0*av.x + w1*bv.x;
    r.y = w0*av.y + w1*bv.y;
    r.z = w0*av.z + w1*bv.z;
    r.w = w0*av.w + w1*bv.w;
    o[i] = r;
}

// ------------------------------------------------------------------
extern "C" void kernel_launch(void* const* d_in, const int* in_sizes, int n_in,
                              void* d_out, int out_size)
{
    const float* x    = (const float*)d_in[0];   // [2048, 1024]
    const float* wqkv = (const float*)d_in[1];   // [96, 1024]
    const float* ws   = (const float*)d_in[2];   // [32, 4096, 1024]
    const float* w2s  = (const float*)d_in[3];   // [32, 1024, 2048]
    float* y = (float*)d_out;                    // [2048, 1024]

    zero_counts_kernel<<<1, 32>>>();

    dim3 gmix(2, T_TOK / 64);
    mix_gemm_kernel<<<gmix, 256>>>(x, wqkv);

    route_kernel<<<T_TOK / 4, 128>>>();

    build_tiles_kernel<<<1, 32>>>();

    dim3 g1(I_DIM / 64, MAX_TILES);              // (32, 64)
    gemm1_fused_kernel<<<g1, NTHREADS>>>(x, ws);

    dim3 g2(H_DIM / 128, MAX_TILES);             // (8, 64)
    gemm2_tc_kernel<<<g2, NTHREADS>>>(w2s);

    combine_kernel<<<T_TOK, 256>>>(y);
}

// round 9
// speedup vs baseline: 1.2747x; 1.2747x over previous
#include <cuda_runtime.h>
#include <math.h>
#include <stdint.h>

// Problem constants
#define T_TOK 2048
#define H_DIM 1024
#define E_EXP 32
#define I_DIM 2048

// Tile config
#define BM 128
#define BN 128
#define BK 16
#define NTHREADS 256
#define MAX_TILES 64
#define SROW 20   // 16 + 4 pad (words)

// -------- scratch (static device globals) --------
__device__ float g_mix[T_TOK * 96];
__device__ float g_topw[T_TOK * 2];
__device__ int   g_counts[E_EXP];
__device__ int   g_list[E_EXP * T_TOK];
__device__ int   g_tile_e[MAX_TILES];
__device__ int   g_tile_m0[MAX_TILES];
__device__ int   g_ntiles;
__device__ float g_gu  [(size_t)T_TOK * 2 * 2 * I_DIM]; // gate/up GEMM out (64 MB)
__device__ float g_act [(size_t)T_TOK * 2 * I_DIM];     // SwiGLU act      (32 MB)
__device__ float g_outp[(size_t)T_TOK * 2 * H_DIM];     // per-pair out    (16 MB)

// ------------------------------------------------------------------
__global__ void zero_counts_kernel() {
    if (threadIdx.x < E_EXP) g_counts[threadIdx.x] = 0;
}

// ------------------------------------------------------------------
// mix = x @ wqkv^T   [2048, 96], K=1024  (fp32, small)
__global__ __launch_bounds__(256) void mix_gemm_kernel(
    const float* __restrict__ x, const float* __restrict__ wqkv)
{
    __shared__ float As[16][64];
    __shared__ float Bs[16][64];
    const int N = 96, K = H_DIM;
    int m0 = blockIdx.y * 64, n0 = blockIdx.x * 64;
    int tid = threadIdx.x;
    int tx = tid & 15, ty = tid >> 4;
    int lm = tid >> 2, lk = (tid & 3) * 4;

    const float* Arow = x + (size_t)(m0 + lm) * K;
    int brow = n0 + lm;
    const float* Brow = wqkv + (size_t)min(brow, N - 1) * K;
    bool bvalid = brow < N;

    float acc[4][4] = {};
    for (int k0 = 0; k0 < K; k0 += 16) {
        float4 av = *(const float4*)(Arow + k0 + lk);
        float4 bv = bvalid ? *(const float4*)(Brow + k0 + lk) : make_float4(0.f,0.f,0.f,0.f);
        As[lk+0][lm]=av.x; As[lk+1][lm]=av.y; As[lk+2][lm]=av.z; As[lk+3][lm]=av.w;
        Bs[lk+0][lm]=bv.x; Bs[lk+1][lm]=bv.y; Bs[lk+2][lm]=bv.z; Bs[lk+3][lm]=bv.w;
        __syncthreads();
        #pragma unroll
        for (int kk = 0; kk < 16; kk++) {
            float4 a = *(const float4*)&As[kk][ty*4];
            float4 b = *(const float4*)&Bs[kk][tx*4];
            float ar[4] = {a.x,a.y,a.z,a.w};
            float br[4] = {b.x,b.y,b.z,b.w};
            #pragma unroll
            for (int i = 0; i < 4; i++)
                #pragma unroll
                for (int j = 0; j < 4; j++)
                    acc[i][j] += ar[i] * br[j];
        }
        __syncthreads();
    }
    #pragma unroll
    for (int i = 0; i < 4; i++) {
        int m = m0 + ty*4 + i;
        #pragma unroll
        for (int j = 0; j < 4; j++) {
            int n = n0 + tx*4 + j;
            if (n < N) g_mix[(size_t)m * 96 + n] = acc[i][j];
        }
    }
}

// ------------------------------------------------------------------
__global__ void route_kernel()
{
    int t = blockIdx.x * 4 + (threadIdx.x >> 5);
    int lane = threadIdx.x & 31;
    if (t >= T_TOK) return;
    const float* mix = g_mix + (size_t)t * 96;
    float q  = mix[lane];
    float kf = mix[32 + lane];
    float vf = mix[64 + lane];

    float m = -INFINITY;
    #pragma unroll
    for (int f = 0; f < 32; f++) {
        float kk = __shfl_sync(0xffffffffu, kf, f);
        m = fmaxf(m, q * kk);
    }
    float s = 0.f, num = 0.f;
    #pragma unroll
    for (int f = 0; f < 32; f++) {
        float kk = __shfl_sync(0xffffffffu, kf, f);
        float vv = __shfl_sync(0xffffffffu, vf, f);
        float p = expf(q * kk - m);
        s += p; num += p * vv;
    }
    float logit = num / s;

    float v1 = logit; int i1 = lane;
    #pragma unroll
    for (int off = 16; off > 0; off >>= 1) {
        float ov = __shfl_xor_sync(0xffffffffu, v1, off);
        int   oi = __shfl_xor_sync(0xffffffffu, i1, off);
        if (ov > v1 || (ov == v1 && oi < i1)) { v1 = ov; i1 = oi; }
    }
    float mval = (lane == i1) ? -INFINITY : logit;
    float v2 = mval; int i2 = lane;
    #pragma unroll
    for (int off = 16; off > 0; off >>= 1) {
        float ov = __shfl_xor_sync(0xffffffffu, v2, off);
        int   oi = __shfl_xor_sync(0xffffffffu, i2, off);
        if (ov > v2 || (ov == v2 && oi < i2)) { v2 = ov; i2 = oi; }
    }

    if (lane == 0) {
        float e2 = expf(v2 - v1);
        float inv = 1.f / (1.f + e2);
        g_topw[t*2 + 0] = inv;
        g_topw[t*2 + 1] = e2 * inv;
        int p1 = atomicAdd(&g_counts[i1], 1);
        g_list[i1 * T_TOK + p1] = t*2 + 0;
        int p2 = atomicAdd(&g_counts[i2], 1);
        g_list[i2 * T_TOK + p2] = t*2 + 1;
    }
}

// ------------------------------------------------------------------
__global__ void build_tiles_kernel()
{
    int e = threadIdx.x;
    int ne = g_counts[e];
    int ct = (ne + BM - 1) / BM;
    int pre = ct;
    #pragma unroll
    for (int off = 1; off < 32; off <<= 1) {
        int v = __shfl_up_sync(0xffffffffu, pre, off);
        if (e >= off) pre += v;
    }
    int start = pre - ct;
    for (int i = 0; i < ct; i++) {
        g_tile_e[start + i]  = e;
        g_tile_m0[start + i] = i * BM;
    }
    if (e == 31) g_ntiles = pre;
}

// ------------------------------------------------------------------
__device__ __forceinline__ uint32_t f2tf32(float f) {
    uint32_t u;
    asm("cvt.rna.tf32.f32 %0, %1;" : "=r"(u) : "f"(f));
    return u;
}

#define LDSM_X4(r0, r1, r2, r3, addr)                                         \
    asm volatile("ldmatrix.sync.aligned.m8n8.x4.shared.b16 {%0,%1,%2,%3}, [%4];" \
        : "=r"(r0), "=r"(r1), "=r"(r2), "=r"(r3) : "r"(addr))

// Gathered GEMM on tensor cores (tf32 m16n8k8), ldmatrix fragment loads.
// MODE 1: g_gu[code,:]   = x[code>>1,:] @ ws_e^T   (K=1024, N=4096)
// MODE 2: g_outp[code,:] = g_act[code,:] @ w2_e^T  (K=2048, N=1024)
template<int MODE>
__global__ __launch_bounds__(NTHREADS, 2) void moe_gemm_tc_kernel(
    const float* __restrict__ Ain, const float* __restrict__ W)
{
    constexpr int KDIM = (MODE == 1) ? H_DIM : I_DIM;
    constexpr int NTOT = (MODE == 1) ? 2 * I_DIM : H_DIM;

    int tile = blockIdx.y;
    if (tile >= g_ntiles) return;
    int e  = g_tile_e[tile];
    int m0 = g_tile_m0[tile];
    int ne = g_counts[e];
    int n0 = blockIdx.x * BN;

    __shared__ uint32_t As[2][BM][SROW];
    __shared__ uint32_t Bs[2][BN][SROW];

    const float* A = (MODE == 1) ? Ain : (const float*)g_act;
    float* C = (MODE == 1) ? (float*)g_gu : (float*)g_outp;
    const float* B = W + (size_t)e * NTOT * KDIM;

    int tid = threadIdx.x;
    int lr  = tid & 127;
    int lc8 = (tid >> 7) * 8;

    int code0 = g_list[e * T_TOK + min(m0 + lr, ne - 1)];
    int arow = (MODE == 1) ? (code0 >> 1) : code0;
    const float* Ap = A + (size_t)arow * KDIM + lc8;
    const float* Bp = B + (size_t)(n0 + lr) * KDIM + lc8;

    int wid = tid >> 5, lane = tid & 31;
    int wm = wid >> 2, wn = wid & 3;       // 2 x 4 warp grid (64x32 per warp)
    int qr = lane >> 2, qc = lane & 3;

    // ldmatrix per-lane source coords
    int a_lr = lane & 15;                       // row offset within 16
    int a_lc = (lane >> 4) * 4;                 // 0 or 4
    int b_lr = ((lane >> 4) << 3) + (lane & 7); // 0..7 / 8..15 pattern
    int b_lc = ((lane >> 3) & 1) * 4;

    uint32_t as_base = (uint32_t)__cvta_generic_to_shared(&As[0][0][0]);
    uint32_t bs_base = (uint32_t)__cvta_generic_to_shared(&Bs[0][0][0]);

    float acc[4][4][4] = {};               // [mt][nt][reg]

    float4 ra0 = *(const float4*)(Ap);
    float4 ra1 = *(const float4*)(Ap + 4);
    float4 rb0 = *(const float4*)(Bp);
    float4 rb1 = *(const float4*)(Bp + 4);

    int p = 0;
    for (int k0 = 0; k0 < KDIM; k0 += BK) {
        *(uint4*)&As[p][lr][lc8]     = make_uint4(f2tf32(ra0.x), f2tf32(ra0.y), f2tf32(ra0.z), f2tf32(ra0.w));
        *(uint4*)&As[p][lr][lc8 + 4] = make_uint4(f2tf32(ra1.x), f2tf32(ra1.y), f2tf32(ra1.z), f2tf32(ra1.w));
        *(uint4*)&Bs[p][lr][lc8]     = make_uint4(f2tf32(rb0.x), f2tf32(rb0.y), f2tf32(rb0.z), f2tf32(rb0.w));
        *(uint4*)&Bs[p][lr][lc8 + 4] = make_uint4(f2tf32(rb1.x), f2tf32(rb1.y), f2tf32(rb1.z), f2tf32(rb1.w));
        __syncthreads();

        if (k0 + BK < KDIM) {
            ra0 = *(const float4*)(Ap + k0 + BK);
            ra1 = *(const float4*)(Ap + k0 + BK + 4);
            rb0 = *(const float4*)(Bp + k0 + BK);
            rb1 = *(const float4*)(Bp + k0 + BK + 4);
        }

        uint32_t abuf = as_base + (uint32_t)(((p ? BM : 0) + wm*64 + a_lr) * SROW + a_lc) * 4u;
        uint32_t bbuf = bs_base + (uint32_t)(((p ? BN : 0) + wn*32 + b_lr) * SROW + b_lc) * 4u;

        #pragma unroll
        for (int kk = 0; kk < BK; kk += 8) {
            uint32_t afr[4][4];
            #pragma unroll
            for (int mt = 0; mt < 4; mt++) {
                LDSM_X4(afr[mt][0], afr[mt][1], afr[mt][2], afr[mt][3],
                        abuf + (uint32_t)((mt*16) * SROW + kk) * 4u);
            }
            uint32_t bfr[4][2];
            #pragma unroll
            for (int ntp = 0; ntp < 4; ntp += 2) {
                LDSM_X4(bfr[ntp][0], bfr[ntp][1], bfr[ntp+1][0], bfr[ntp+1][1],
                        bbuf + (uint32_t)((ntp*8) * SROW + kk) * 4u);
            }
            #pragma unroll
            for (int mt = 0; mt < 4; mt++)
                #pragma unroll
                for (int nt = 0; nt < 4; nt++) {
                    asm volatile(
                        "mma.sync.aligned.m16n8k8.row.col.f32.tf32.tf32.f32 "
                        "{%0,%1,%2,%3}, {%4,%5,%6,%7}, {%8,%9}, {%0,%1,%2,%3};"
                        : "+f"(acc[mt][nt][0]), "+f"(acc[mt][nt][1]),
                          "+f"(acc[mt][nt][2]), "+f"(acc[mt][nt][3])
                        : "r"(afr[mt][0]), "r"(afr[mt][1]),
                          "r"(afr[mt][2]), "r"(afr[mt][3]),
                          "r"(bfr[nt][0]), "r"(bfr[nt][1]));
                }
        }
        p ^= 1;
    }

    // epilogue
    #pragma unroll
    for (int mt = 0; mt < 4; mt++) {
        int r0 = m0 + wm*64 + mt*16 + qr;
        int r1 = r0 + 8;
        bool v0 = r0 < ne, v1 = r1 < ne;
        int c0 = v0 ? g_list[e * T_TOK + r0] : 0;
        int c1 = v1 ? g_list[e * T_TOK + r1] : 0;
        float* d0 = C + (size_t)c0 * NTOT + n0 + wn*32;
        float* d1 = C + (size_t)c1 * NTOT + n0 + wn*32;
        #pragma unroll
        for (int nt = 0; nt < 4; nt++) {
            int col = nt*8 + 2*qc;
            if (v0) *(float2*)(d0 + col) = make_float2(acc[mt][nt][0], acc[mt][nt][1]);
            if (v1) *(float2*)(d1 + col) = make_float2(acc[mt][nt][2], acc[mt][nt][3]);
        }
    }
}

// ------------------------------------------------------------------
__global__ void swiglu_kernel()
{
    int c = blockIdx.x;
    const float4* gp = (const float4*)(g_gu + (size_t)c * (2 * I_DIM));
    const float4* up = (const float4*)(g_gu + (size_t)c * (2 * I_DIM) + I_DIM);
    float4* dst = (float4*)(g_act + (size_t)c * I_DIM);
    #pragma unroll
    for (int j = threadIdx.x; j < I_DIM / 4; j += 256) {
        float4 g = gp[j], u = up[j];
        float4 r;
        r.x = (g.x / (1.f + expf(-g.x))) * u.x;
        r.y = (g.y / (1.f + expf(-g.y))) * u.y;
        r.z = (g.z / (1.f + expf(-g.z))) * u.z;
        r.w = (g.w / (1.f + expf(-g.w))) * u.w;
        dst[j] = r;
    }
}

// ------------------------------------------------------------------
__global__ void combine_kernel(float* __restrict__ y)
{
    int t = blockIdx.x;
    float w0 = g_topw[t*2 + 0];
    float w1 = g_topw[t*2 + 1];
    const float4* a = (const float4*)(g_outp + (size_t)(t*2    ) * H_DIM);
    const float4* b = (const float4*)(g_outp + (size_t)(t*2 + 1) * H_DIM);
    float4* o = (float4*)(y + (size_t)t * H_DIM);
    int i = threadIdx.x;
    float4 av = a[i], bv = b[i];
    float4 r;
    r.x = w0*av.x + w1*bv.x;
    r.y = w0*av.y + w1*bv.y;
    r.z = w0*av.z + w1*bv.z;
    r.w = w0*av.w + w1*bv.w;
    o[i] = r;
}

// ------------------------------------------------------------------
extern "C" void kernel_launch(void* const* d_in, const int* in_sizes, int n_in,
                              void* d_out, int out_size)
{
    const float* x    = (const float*)d_in[0];   // [2048, 1024]
    const float* wqkv = (const float*)d_in[1];   // [96, 1024]
    const float* ws   = (const float*)d_in[2];   // [32, 4096, 1024]
    const float* w2s  = (const float*)d_in[3];   // [32, 1024, 2048]
    float* y = (float*)d_out;                    // [2048, 1024]

    zero_counts_kernel<<<1, 32>>>();

    dim3 gmix(2, T_TOK / 64);
    mix_gemm_kernel<<<gmix, 256>>>(x, wqkv);

    route_kernel<<<T_TOK / 4, 128>>>();

    build_tiles_kernel<<<1, 32>>>();

    dim3 g1((2 * I_DIM) / BN, MAX_TILES);        // (32, 64)
    moe_gemm_tc_kernel<1><<<g1, NTHREADS>>>(x, ws);

    swiglu_kernel<<<T_TOK * 2, 256>>>();

    dim3 g2(H_DIM / BN, MAX_TILES);              // (8, 64)
    moe_gemm_tc_kernel<2><<<g2, NTHREADS>>>(nullptr, w2s);

    combine_kernel<<<T_TOK, 256>>>(y);
}